// round 13
// baseline (speedup 1.0000x reference)
#include <cuda_runtime.h>

#define DD     262144     // 512*512
#define NB     128        // batch
#define NENV   4
#define KSEL   26214      // floor(0.1 * 512 * 512)
#define NBIN   65536
#define NCRS   1024       // coarse bins = fkey >> 22
#define PW_BLOCKS 592     // persistent writers: ~half the SM slots each
#define PW_ITEMS  (NB * (DD / 1024))   // 32768 work items (b, chunk)

// Scratch (allocation-free: __device__ globals, zero-initialized at module load)
__device__ unsigned g_hist[NENV][NBIN];    // fine pass 1 (hi 16 bits)
__device__ unsigned g_hist2[NENV][NBIN];   // fine pass 2 (lo 16 bits)
__device__ unsigned g_coarse[NENV][NCRS];  // chunk sums of g_hist  (fkey>>22)
__device__ unsigned g_coarse2[NENV][NCRS]; // chunk sums of g_hist2 (lo>>6)
__device__ unsigned g_binhi[NENV];
__device__ unsigned g_rank[NENV];
__device__ unsigned g_kth[NENV];           // exact key of k-th largest per env

// Monotone mapping: float total order -> unsigned total order
__device__ __forceinline__ unsigned fkey(float f) {
    unsigned u = __float_as_uint(f);
    return (u & 0x80000000u) ? ~u : (u | 0x80000000u);
}
__device__ __forceinline__ float sigm(float x) {
    return __fdividef(1.0f, 1.0f + __expf(-x));   // MUFU EX2 + fast RCP
}
__device__ __forceinline__ float4 madd(float4 a, float4 b) {
    float4 m; m.x = a.x + b.x; m.y = a.y + b.y; m.z = a.z + b.z; m.w = a.w + b.w;
    return m;
}

// Hi-16 fine histogram + coarse chunk sums (smem-agg).
// Also zeroes g_hist2/g_coarse2 for this call's pass 2.
// Requires g_hist/g_coarse == 0 on entry (load-time zero; re-zeroed by k_hist2).
__global__ void k_build(const float* __restrict__ base, const float* __restrict__ deltas) {
    __shared__ unsigned sc[NCRS];
    int e = blockIdx.y;
    int t = threadIdx.x;                                // 0..255
    int tid = blockIdx.x * 256 + t;                     // 0..65535 per env slice
    sc[t] = 0u; sc[t + 256] = 0u; sc[t + 512] = 0u; sc[t + 768] = 0u;
    (&g_hist2[0][0])[e * NBIN + tid] = 0u;              // coalesced free zeroing
    if (tid < NCRS) g_coarse2[e][tid] = 0u;
    __syncthreads();

    int i = tid * 4;
    float4 m = madd(*(const float4*)(base + i),
                    *(const float4*)(deltas + (size_t)e * DD + i));
    unsigned k0 = fkey(m.x), k1 = fkey(m.y), k2 = fkey(m.z), k3 = fkey(m.w);
    atomicAdd(&g_hist[e][k0 >> 16], 1u);
    atomicAdd(&g_hist[e][k1 >> 16], 1u);
    atomicAdd(&g_hist[e][k2 >> 16], 1u);
    atomicAdd(&g_hist[e][k3 >> 16], 1u);
    atomicAdd(&sc[k0 >> 22], 1u);
    atomicAdd(&sc[k1 >> 22], 1u);
    atomicAdd(&sc[k2 >> 22], 1u);
    atomicAdd(&sc[k3 >> 22], 1u);
    __syncthreads();
    #pragma unroll
    for (int j = 0; j < 4; j++) {                       // flush nonzero coarse bins
        unsigned v = sc[t + j * 256];
        if (v) atomicAdd(&g_coarse[e][t + j * 256], v);
    }
}

// Rank-select using precomputed coarse sums.
// phase 0: g_coarse/g_hist   -> (binhi, remaining rank)
// phase 1: g_coarse2/g_hist2 -> exact kth key
__global__ void k_scan(int phase) {
    int e = blockIdx.x;
    int t = threadIdx.x;
    int lane = t & 31, w = t >> 5;
    const unsigned* co = (phase == 0) ? &g_coarse[e][0] : &g_coarse2[e][0];
    const unsigned* h  = (phase == 0) ? &g_hist[e][0]   : &g_hist2[e][0];
    __shared__ unsigned ss[NCRS];
    __shared__ unsigned sel[2];       // [chunk id, cum above chunk]
    __shared__ unsigned bins64[64];

    ss[t] = co[t];
    __syncthreads();
    for (int off = 1; off < NCRS; off <<= 1) {          // inclusive suffix sum
        unsigned v = (t + off < NCRS) ? ss[t + off] : 0u;
        __syncthreads();
        ss[t] += v;
        __syncthreads();
    }

    unsigned target = (phase == 0) ? (unsigned)KSEL : g_rank[e];
    unsigned above = (t < NCRS - 1) ? ss[t + 1] : 0u;
    if (ss[t] >= target && above < target) { sel[0] = (unsigned)t; sel[1] = above; }
    __syncthreads();

    unsigned cstar = sel[0], cum0 = sel[1];
    if (w == 0) {                                       // coalesced winning chunk
        bins64[lane]      = h[cstar * 64 + lane];
        bins64[lane + 32] = h[cstar * 64 + 32 + lane];
    }
    __syncthreads();

    if (t == 0) {
        unsigned cum = cum0;
        unsigned bin = cstar * 64;
        for (int j = 63; j >= 0; j--) {
            unsigned v = bins64[j];
            if (cum + v >= target) { bin = cstar * 64 + j; break; }
            cum += v;
        }
        if (phase == 0) { g_binhi[e] = bin; g_rank[e] = target - cum; }
        else            { g_kth[e]  = (g_binhi[e] << 16) | bin; }
    }
}

// Lo-16 fine histogram (restricted to selected hi-bin) + coarse sums.
// Recomputes m from base+deltas (L2-hot). Re-zeroes g_hist/g_coarse for replay.
__global__ void k_hist2(const float* __restrict__ base, const float* __restrict__ deltas) {
    __shared__ unsigned sc[NCRS];
    int e = blockIdx.y;
    unsigned hi = g_binhi[e];
    int t = threadIdx.x;
    int tid = blockIdx.x * 256 + t;
    sc[t] = 0u; sc[t + 256] = 0u; sc[t + 512] = 0u; sc[t + 768] = 0u;
    (&g_hist[0][0])[e * NBIN + tid] = 0u;               // coalesced free zeroing
    if (tid < NCRS) g_coarse[e][tid] = 0u;
    __syncthreads();

    int i = tid * 4;
    float4 m = madd(*(const float4*)(base + i),
                    *(const float4*)(deltas + (size_t)e * DD + i));
    unsigned k0 = fkey(m.x), k1 = fkey(m.y), k2 = fkey(m.z), k3 = fkey(m.w);
    if ((k0 >> 16) == hi) { atomicAdd(&g_hist2[e][k0 & 0xFFFFu], 1u); atomicAdd(&sc[(k0 & 0xFFFFu) >> 6], 1u); }
    if ((k1 >> 16) == hi) { atomicAdd(&g_hist2[e][k1 & 0xFFFFu], 1u); atomicAdd(&sc[(k1 & 0xFFFFu) >> 6], 1u); }
    if ((k2 >> 16) == hi) { atomicAdd(&g_hist2[e][k2 & 0xFFFFu], 1u); atomicAdd(&sc[(k2 & 0xFFFFu) >> 6], 1u); }
    if ((k3 >> 16) == hi) { atomicAdd(&g_hist2[e][k3 & 0xFFFFu], 1u); atomicAdd(&sc[(k3 & 0xFFFFu) >> 6], 1u); }
    __syncthreads();
    #pragma unroll
    for (int j = 0; j < 4; j++) {
        unsigned v = sc[t + j * 256];
        if (v) atomicAdd(&g_coarse2[e][t + j * 256], v);
    }
}

// A_logits + A_soft writer: PERSISTENT grid-stride with PW_BLOCKS (~half the
// SM slots), so the selection chain co-schedules on the free slots. 268 MB.
__global__ void k_outLS(const int* __restrict__ env_idx,
                        float* __restrict__ outL, float* __restrict__ outS,
                        const float* __restrict__ base, const float* __restrict__ deltas) {
    int t = threadIdx.x;
    for (int item = blockIdx.x; item < PW_ITEMS; item += PW_BLOCKS) {
        int b = item >> 8;                  // row
        int c = item & 255;                 // 1024-element chunk within row
        int e = __ldg(&env_idx[b]);
        size_t i = ((size_t)c * 256 + t) * 4;
        float4 m = madd(*(const float4*)(base + i),
                        *(const float4*)(deltas + (size_t)e * DD + i));
        float4 s;
        s.x = sigm(m.x); s.y = sigm(m.y); s.z = sigm(m.z); s.w = sigm(m.w);
        size_t off = (size_t)b * DD + i;
        *(float4*)(outL + off) = m;
        *(float4*)(outS + off) = s;
    }
}

// A writer: needs only g_kth. Also persistent at PW_BLOCKS so it slots into
// the half of the machine not held by k_outLS during the overlap tail. 134 MB.
__global__ void k_outA(const int* __restrict__ env_idx,
                       float* __restrict__ outA,
                       const float* __restrict__ base, const float* __restrict__ deltas) {
    int t = threadIdx.x;
    for (int item = blockIdx.x; item < PW_ITEMS; item += PW_BLOCKS) {
        int b = item >> 8;
        int c = item & 255;
        int e = __ldg(&env_idx[b]);
        unsigned kth = g_kth[e];
        size_t i = ((size_t)c * 256 + t) * 4;
        float4 m = madd(*(const float4*)(base + i),
                        *(const float4*)(deltas + (size_t)e * DD + i));
        float4 a;
        a.x = (fkey(m.x) >= kth) ? sigm(m.x) : 0.0f;
        a.y = (fkey(m.y) >= kth) ? sigm(m.y) : 0.0f;
        a.z = (fkey(m.z) >= kth) ? sigm(m.z) : 0.0f;
        a.w = (fkey(m.w) >= kth) ? sigm(m.w) : 0.0f;
        *(float4*)(outA + (size_t)b * DD + i) = a;
    }
}

extern "C" void kernel_launch(void* const* d_in, const int* in_sizes, int n_in,
                              void* d_out, int out_size) {
    // Side stream + events, created once on the (uncaptured) correctness call,
    // reused during capture via the standard fork-join pattern. No device allocs.
    static cudaStream_t s1 = nullptr;
    static cudaEvent_t evFork = nullptr, evJoin = nullptr;
    if (s1 == nullptr) {
        cudaStreamCreateWithFlags(&s1, cudaStreamNonBlocking);
        cudaEventCreateWithFlags(&evFork, cudaEventDisableTiming);
        cudaEventCreateWithFlags(&evJoin, cudaEventDisableTiming);
    }

    const float* base   = nullptr;
    const float* deltas = nullptr;
    const int*   env    = nullptr;
    for (int i = 0; i < n_in; i++) {
        if      (in_sizes[i] == DD)        base   = (const float*)d_in[i];
        else if (in_sizes[i] == NENV * DD) deltas = (const float*)d_in[i];
        else if (in_sizes[i] == NB)        env    = (const int*)d_in[i];
        // z_s (131072 elems) unused by the reference outputs
    }

    float* outA = (float*)d_out;            // tuple order: (A, A_logits, A_soft)
    float* outL = outA + (size_t)NB * DD;
    float* outS = outL + (size_t)NB * DD;

    // Fork: persistent L/S writer occupies ~half the machine on s1.
    cudaEventRecord(evFork, 0);
    cudaStreamWaitEvent(s1, evFork, 0);
    k_outLS<<<PW_BLOCKS, 256, 0, s1>>>(env, outL, outS, base, deltas);

    // Selection chain co-schedules on the remaining SM slots.
    dim3 gb(DD / 1024, NENV);               // (256, 4)
    k_build<<<gb, 256>>>(base, deltas);
    k_scan<<<NENV, NCRS>>>(0);
    k_hist2<<<gb, 256>>>(base, deltas);
    k_scan<<<NENV, NCRS>>>(1);
    k_outA<<<PW_BLOCKS, 256>>>(env, outA, base, deltas);

    // Join: main stream completion implies s1 completion.
    cudaEventRecord(evJoin, s1);
    cudaStreamWaitEvent(0, evJoin, 0);
}